// round 2
// baseline (speedup 1.0000x reference)
#include <cuda_runtime.h>

#define NB 128
#define NT 256
#define BZ 32
#define TT 2048
#define FF 128
#define HH 256
#define SLOT (BZ*HH)
#define MEMOFF ((TT+1)*SLOT)

// shared memory float offsets
#define O_SA 0                      // sa[32][385]  (x: k<128, h: k in [128,384))
#define O_CB (O_SA+32*385)          // cbuf[32][257] (full c vector per batch)
#define O_WA (O_CB+32*257)          // WA[384][8]   r=u*4+q, grow=q*H+j0+u
#define O_WP (O_WA+384*8)           // WP[256][4]   r=u*2+p (p=0:Wci,1:Wcf)
#define O_WO (O_WP+256*4)           // WO[256][2]
#define O_BA (O_WO+256*2)           // ba[8] = bx+bh
#define O_BP (O_BA+8)               // bp[4]
#define O_BO (O_BP+4)               // bo[4]
#define O_PA (O_BO+4)               // PA[8][8][32]
#define O_PP (O_PA+2048)            // PP[8][4][32]
#define O_PO (O_PP+1024)            // PO[8][2][32]
#define O_YA (O_PO+512)             // yAs[8][32]
#define O_YP (O_YA+256)             // yPs[4][32]
#define O_OP (O_YP+128)             // opre[2][32]
#define SMF  (O_OP+64)
#define SMB  (SMF*4)

__device__ unsigned g_bar;

__device__ __forceinline__ float sgm(float v){ return 1.f/(1.f+expf(-v)); }

// grid-wide barrier (all 128 CTAs co-resident: 1 CTA/SM, grid < 148 SMs)
__device__ __forceinline__ void gsync(unsigned &tgt){
  __syncthreads();
  if (threadIdx.x==0){
    tgt += NB;
    __threadfence();
    atomicAdd(&g_bar, 1u);
    unsigned v;
    do { asm volatile("ld.acquire.gpu.u32 %0,[%1];" : "=r"(v) : "l"(&g_bar) : "memory"); } while (v < tgt);
  }
  __syncthreads();
}

__global__ void zk(float* __restrict__ out){
  int i = blockIdx.x*blockDim.x + threadIdx.x;
  if (i==0) g_bar = 0u;
  if (i < SLOT){ out[i]=0.f; out[MEMOFF+i]=0.f; }  // h0 = c0 = 0
}

__global__ void __launch_bounds__(NT,1) lstm(
  const float* __restrict__ x,  const float* __restrict__ Wx,  const float* __restrict__ bx,
  const float* __restrict__ Wh, const float* __restrict__ bh,
  const float* __restrict__ Wci,const float* __restrict__ bci,
  const float* __restrict__ Wcf,const float* __restrict__ bcf,
  const float* __restrict__ Wco,const float* __restrict__ bco,
  float* __restrict__ out)
{
  extern __shared__ float sm[];
  const int tid=threadIdx.x, warp=tid>>5, lane=tid&31;
  const int j0 = blockIdx.x*2;

  // ---- one-time weight staging (transposed for broadcast loads) ----
  for (int i=tid; i<384*8; i+=NT){
    int k=i>>3, r=i&7, u=r>>2, q=r&3, g=q*HH+j0+u;
    sm[O_WA+i] = (k<FF) ? Wx[g*FF+k] : Wh[g*HH+k-FF];
  }
  for (int i=tid; i<256*4; i+=NT){
    int k=i>>2, r=i&3, u=r>>1, p=r&1;
    sm[O_WP+i] = (p?Wcf:Wci)[(j0+u)*HH+k];
  }
  for (int i=tid; i<256*2; i+=NT){
    int k=i>>1, u=i&1; sm[O_WO+i] = Wco[(j0+u)*HH+k];
  }
  if (tid<8){ int u=tid>>2,q=tid&3,g=q*HH+j0+u; sm[O_BA+tid]=bx[g]+bh[g]; }
  else if (tid<12){ int r=tid-8,u=r>>1; sm[O_BP+r]=((r&1)?bcf:bci)[j0+u]; }
  else if (tid<14){ sm[O_BO+tid-12]=bco[j0+tid-12]; }

  // c0 = 0 in smem (stays resident; re-staged from mem[] each step after barrier 1)
  for (int i=tid; i<32*257; i+=NT) sm[O_CB+i]=0.f;

  unsigned tgt = 0;
  float* hid = out;
  float* mem = out + MEMOFF;
  const int bs = tid>>3, f0 = tid&7;   // staging map: 4 batches x 8 float4-cols per warp
  __syncthreads();

  for (int s=0; s<TT; s++){
    // ---- stage x_t (k<128) and h_s (k>=128) into sa ----
    #pragma unroll
    for (int it=0; it<4; it++){
      int fg=f0+it*8;
      float4 v = *(const float4*)(x + ((long)bs*TT + s)*FF + fg*4);
      float* d = sm + O_SA + bs*385 + fg*4;
      d[0]=v.x; d[1]=v.y; d[2]=v.z; d[3]=v.w;
    }
    #pragma unroll
    for (int it=0; it<8; it++){
      int fg=f0+it*8;
      float4 v = *(const float4*)(hid + (long)s*SLOT + bs*HH + fg*4);
      float* d = sm + O_SA + bs*385 + FF + fg*4;
      d[0]=v.x; d[1]=v.y; d[2]=v.z; d[3]=v.w;
    }
    __syncthreads();

    // ---- phase A: 8 gate rows, K=384 (x|h), lane=batch, warp=k-chunk ----
    float acc[8];
    #pragma unroll
    for (int r=0;r<8;r++) acc[r]=0.f;
    for (int k=warp*48; k<warp*48+48; k++){
      float sv = sm[O_SA + lane*385 + k];
      float4 w0 = *(float4*)&sm[O_WA + k*8];
      float4 w1 = *(float4*)&sm[O_WA + k*8+4];
      acc[0]+=w0.x*sv; acc[1]+=w0.y*sv; acc[2]+=w0.z*sv; acc[3]+=w0.w*sv;
      acc[4]+=w1.x*sv; acc[5]+=w1.y*sv; acc[6]+=w1.z*sv; acc[7]+=w1.w*sv;
    }
    #pragma unroll
    for (int r=0;r<8;r++) sm[O_PA + warp*256 + r*32 + lane] = acc[r];

    // peephole dots over c (K=256)
    float ap[4];
    #pragma unroll
    for (int r=0;r<4;r++) ap[r]=0.f;
    for (int k=warp*32; k<warp*32+32; k++){
      float cv = sm[O_CB + lane*257 + k];
      float4 w = *(float4*)&sm[O_WP + k*4];
      ap[0]+=w.x*cv; ap[1]+=w.y*cv; ap[2]+=w.z*cv; ap[3]+=w.w*cv;
    }
    #pragma unroll
    for (int r=0;r<4;r++) sm[O_PP + warp*128 + r*32 + lane] = ap[r];
    __syncthreads();

    // ---- cross-warp reduce ----
    {
      int r=tid>>5, b=lane;
      float v = sm[O_BA+r];
      #pragma unroll
      for (int w=0;w<8;w++) v += sm[O_PA + w*256 + r*32 + b];
      sm[O_YA + r*32 + b] = v;
    }
    if (tid<128){
      int r=tid>>5, b=lane;
      float v = sm[O_BP+r];
      #pragma unroll
      for (int w=0;w<8;w++) v += sm[O_PP + w*128 + r*32 + b];
      sm[O_YP + r*32 + b] = v;
    }
    __syncthreads();

    // ---- gates, c_new ----
    if (tid<64){
      int u=tid>>5, b=lane;
      float ii = sgm (sm[O_YA+(u*4+0)*32+b] + sm[O_YP+(u*2+0)*32+b]);
      float ff = sgm (sm[O_YA+(u*4+1)*32+b] + sm[O_YP+(u*2+1)*32+b]);
      float gg = tanhf(sm[O_YA+(u*4+3)*32+b]);
      float co = sm[O_CB + b*257 + j0+u];
      float cn = ff*co + ii*gg;
      mem[(long)(s+1)*SLOT + b*HH + j0+u] = cn;
      sm[O_OP + u*32 + b] = sm[O_YA+(u*4+2)*32+b];   // o-gate pre-activation
    }
    gsync(tgt);   // all CTAs' c_new visible

    // ---- stage full c_new (becomes next step's c) ----
    #pragma unroll
    for (int it=0; it<8; it++){
      int fg=f0+it*8;
      float4 v = *(const float4*)(mem + (long)(s+1)*SLOT + bs*HH + fg*4);
      float* d = sm + O_CB + bs*257 + fg*4;
      d[0]=v.x; d[1]=v.y; d[2]=v.z; d[3]=v.w;
    }
    __syncthreads();

    // ---- phase B: o-gate peephole over c_new, then h_new ----
    float ao0=0.f, ao1=0.f;
    for (int k=warp*32; k<warp*32+32; k++){
      float cv = sm[O_CB + lane*257 + k];
      float2 w = *(float2*)&sm[O_WO + k*2];
      ao0 += w.x*cv; ao1 += w.y*cv;
    }
    sm[O_PO + warp*64 + lane]      = ao0;
    sm[O_PO + warp*64 + 32 + lane] = ao1;
    __syncthreads();
    if (tid<64){
      int u=tid>>5, b=lane;
      float v = sm[O_BO+u] + sm[O_OP + u*32 + b];
      #pragma unroll
      for (int w=0;w<8;w++) v += sm[O_PO + w*64 + u*32 + b];
      float oo = sgm(v);
      float cn = sm[O_CB + b*257 + j0+u];
      hid[(long)(s+1)*SLOT + b*HH + j0+u] = oo*tanhf(cn);
    }
    gsync(tgt);   // all CTAs' h_new visible before next step stages h
  }
}

extern "C" void kernel_launch(void* const* d_in, const int* in_sizes, int n_in,
                              void* d_out, int out_size) {
  cudaFuncSetAttribute(lstm, cudaFuncAttributeMaxDynamicSharedMemorySize, SMB);
  float* out = (float*)d_out;
  zk<<<32, 256>>>(out);
  lstm<<<NB, NT, SMB>>>(
    (const float*)d_in[0], (const float*)d_in[1], (const float*)d_in[2],
    (const float*)d_in[3], (const float*)d_in[4],
    (const float*)d_in[5], (const float*)d_in[6],
    (const float*)d_in[7], (const float*)d_in[8],
    (const float*)d_in[9], (const float*)d_in[10],
    out);
}